// round 16
// baseline (speedup 1.0000x reference)
#include <cuda_runtime.h>
#include <cuda_fp16.h>
#include <cstdint>

#define NNODES 100000
#define NEDGES 1600000
#define DIN    64
#define DH     128
#define NG     64
#define NEMB   64
#define SCANB  1024
#define NBLK   ((NNODES + SCANB - 1) / SCANB)   // 98
#define ASTRIDE 256                              // fp16 operand row stride (halves)
#define NTILES ((NNODES + 127) / 128)            // 782

// fused prep kernel block ranges
#define HIST_B  ((NEDGES + 255) / 256)                 // 6250
#define X2H_B   ((NNODES * (DIN / 2) + 255) / 256)     // 12500
#define PREPW_N (128 * 128 + 2 * 128 * 256)            // 81920
#define PREPW_B ((PREPW_N + 255) / 256)                // 320

// ---------------- scratch (static device memory; no allocation) ----------------
__device__ float  g_h[(size_t)NNODES * DH];
__device__ __align__(16) __half g_Ahi[(size_t)NNODES * ASTRIDE];
__device__ __align__(16) __half g_xh [(size_t)NNODES * DIN];     // fp16 copy of x
__device__ __align__(16) __half g_W1h[128 * ASTRIDE];
__device__ __align__(16) __half g_W2h[128 * ASTRIDE];
__device__ __align__(16) __half g_W3h[128 * ASTRIDE];
__device__ int    g_deg_i[NNODES];      // zeroed inside scan kernel for next call
__device__ int    g_off[NNODES + 1];
__device__ int    g_cursor[NNODES];
__device__ int    g_aggr[NBLK];
__device__ int    g_scan_cnt;
__device__ int    g_csrc[NEDGES];

// ---------------- fused prep: dst-histogram | x->fp16 (+ self half) | W->fp16 ----------------
__global__ void prep_fused(const int* __restrict__ dst, const float* __restrict__ x,
                           const float* __restrict__ Wl1, const float* __restrict__ Wr1,
                           const float* __restrict__ Wl2, const float* __restrict__ Wr2,
                           const float* __restrict__ Wl3, const float* __restrict__ Wr3) {
    int b = blockIdx.x;
    if (b < HIST_B) {
        int e = b * 256 + threadIdx.x;
        if (e < NEDGES) atomicAdd(&g_deg_i[dst[e]], 1);
        return;
    }
    b -= HIST_B;
    if (b < X2H_B) {
        int i = b * 256 + threadIdx.x;               // half2 index
        if (i < NNODES * (DIN / 2)) {
            int n = i >> 5, cp = i & 31;
            float2 v = ((const float2*)x)[(size_t)n * 32 + cp];
            __half2 hv = __float22half2_rn(v);
            *(__half2*)&g_xh [(size_t)n * DIN + cp * 2]           = hv;
            *(__half2*)&g_Ahi[(size_t)n * ASTRIDE + 64 + cp * 2]  = hv;  // self half
        }
        return;
    }
    b -= X2H_B;
    {
        int idx = b * 256 + threadIdx.x;
        const float *Wl, *Wr;
        __half *wh;
        int K, local;
        if (idx < 128 * 128) {
            Wl = Wl1; Wr = Wr1; K = 64;  local = idx; wh = g_W1h;
        } else if (idx < 128 * 128 + 128 * 256) {
            Wl = Wl2; Wr = Wr2; K = 128; local = idx - 128 * 128; wh = g_W2h;
        } else if (idx < PREPW_N) {
            Wl = Wl3; Wr = Wr3; K = 128; local = idx - 128 * 128 - 128 * 256; wh = g_W3h;
        } else return;
        int Ktot = 2 * K;
        int n = local / Ktot, k = local % Ktot;
        float w = (k < K) ? Wl[k * 128 + n] : Wr[(k - K) * 128 + n];
        wh[(size_t)n * ASTRIDE + k] = __float2half_rn(w);
    }
}

// ---------------- fused exclusive scan (decoupled aggregates, 98 co-resident blocks) ----------------
__global__ __launch_bounds__(SCANB) void scan_fused_kernel() {
    __shared__ int sh[SCANB];
    __shared__ int s_base;
    int b = blockIdx.x;
    int i = b * SCANB + threadIdx.x;
    int v = (i < NNODES) ? g_deg_i[i] : 0;
    int x = v;
    sh[threadIdx.x] = x;
    __syncthreads();
#pragma unroll
    for (int d = 1; d < SCANB; d <<= 1) {
        int t = (threadIdx.x >= d) ? sh[threadIdx.x - d] : 0;
        __syncthreads();
        x += t;
        sh[threadIdx.x] = x;
        __syncthreads();
    }
    if (threadIdx.x == SCANB - 1) {
        g_aggr[b] = x;
        __threadfence();
        atomicAdd(&g_scan_cnt, 1);
    }
    if (threadIdx.x == 0) {
        while (atomicAdd(&g_scan_cnt, 0) < NBLK) { }
    }
    __syncthreads();
    __shared__ int red[128];
    if (threadIdx.x < 128) {
        int t = threadIdx.x;
        red[t] = (t < b) ? g_aggr[t] : 0;
    }
    __syncthreads();
    if (threadIdx.x < 64)  red[threadIdx.x] += red[threadIdx.x + 64];
    __syncthreads();
    if (threadIdx.x < 32) {
        int s = red[threadIdx.x] + red[threadIdx.x + 32];
#pragma unroll
        for (int o = 16; o > 0; o >>= 1)
            s += __shfl_down_sync(0xFFFFFFFF, s, o);
        if (threadIdx.x == 0) s_base = s;
    }
    __syncthreads();
    int base = s_base;
    if (i < NNODES) {
        int o = base + x - v;
        g_off[i] = o;
        g_cursor[i] = o;
        g_deg_i[i] = 0;
    }
    if (i == 0) g_off[NNODES] = NEDGES;
}

__global__ void fill_kernel(const int* __restrict__ src, const int* __restrict__ dst) {
    int e = blockIdx.x * blockDim.x + threadIdx.x;
    if (e == 0) g_scan_cnt = 0;
    if (e < NEDGES) {
        int t = dst[e];
        int slot = atomicAdd(&g_cursor[t], 1);
        g_csrc[slot] = src[e];
    }
}

// ---------------- layer-1 aggregation: fp16 gather, 8-edge unroll (MLP 4/lane) ----------------
__global__ __launch_bounds__(256) void agg64x_kernel() {
    int wid = (blockIdx.x * blockDim.x + threadIdx.x) >> 5;
    int lane = threadIdx.x & 31;
    if (wid >= NNODES) return;
    int half = lane >> 4, sub = lane & 15;
    int s = g_off[wid], e = g_off[wid + 1];
    float ax = 0.f, ay = 0.f, az = 0.f, aw = 0.f;
    const uint2* xh = (const uint2*)g_xh;     // 16 uint2 per 64-col row
    int i = s;
    for (; i + 8 <= e; i += 8) {
        int n0 = g_csrc[i     + half];
        int n1 = g_csrc[i + 2 + half];
        int n2 = g_csrc[i + 4 + half];
        int n3 = g_csrc[i + 6 + half];
        uint2 u0 = xh[(size_t)n0 * 16 + sub];
        uint2 u1 = xh[(size_t)n1 * 16 + sub];
        uint2 u2 = xh[(size_t)n2 * 16 + sub];
        uint2 u3 = xh[(size_t)n3 * 16 + sub];
        float2 p;
        p = __half22float2(*(__half2*)&u0.x); ax += p.x; ay += p.y;
        p = __half22float2(*(__half2*)&u0.y); az += p.x; aw += p.y;
        p = __half22float2(*(__half2*)&u1.x); ax += p.x; ay += p.y;
        p = __half22float2(*(__half2*)&u1.y); az += p.x; aw += p.y;
        p = __half22float2(*(__half2*)&u2.x); ax += p.x; ay += p.y;
        p = __half22float2(*(__half2*)&u2.y); az += p.x; aw += p.y;
        p = __half22float2(*(__half2*)&u3.x); ax += p.x; ay += p.y;
        p = __half22float2(*(__half2*)&u3.y); az += p.x; aw += p.y;
    }
    for (; i + 4 <= e; i += 4) {
        int n0 = g_csrc[i + half];
        int n1 = g_csrc[i + 2 + half];
        uint2 u0 = xh[(size_t)n0 * 16 + sub];
        uint2 u1 = xh[(size_t)n1 * 16 + sub];
        float2 p;
        p = __half22float2(*(__half2*)&u0.x); ax += p.x; ay += p.y;
        p = __half22float2(*(__half2*)&u0.y); az += p.x; aw += p.y;
        p = __half22float2(*(__half2*)&u1.x); ax += p.x; ay += p.y;
        p = __half22float2(*(__half2*)&u1.y); az += p.x; aw += p.y;
    }
    for (; i < e; i += 2) {
        if (i + half < e) {
            int n = g_csrc[i + half];
            uint2 u = xh[(size_t)n * 16 + sub];
            float2 p;
            p = __half22float2(*(__half2*)&u.x); ax += p.x; ay += p.y;
            p = __half22float2(*(__half2*)&u.y); az += p.x; aw += p.y;
        }
    }
    ax += __shfl_xor_sync(0xFFFFFFFF, ax, 16);
    ay += __shfl_xor_sync(0xFFFFFFFF, ay, 16);
    az += __shfl_xor_sync(0xFFFFFFFF, az, 16);
    aw += __shfl_xor_sync(0xFFFFFFFF, aw, 16);
    if (half == 0) {
        float inv = 1.0f / (float)max(e - s, 1);
        __half2 h0 = __float22half2_rn(make_float2(ax * inv, ay * inv));
        __half2 h1 = __float22half2_rn(make_float2(az * inv, aw * inv));
        uint2 uh;
        uh.x = *(uint32_t*)&h0; uh.y = *(uint32_t*)&h1;
        *(uint2*)&g_Ahi[(size_t)wid * ASTRIDE + sub * 4] = uh;
    }
}

// ---------------- layer-2/3 aggregation: fp16 shadow, 8-edge unroll (MLP 4/lane) ----------------
__global__ __launch_bounds__(256) void agg128h_kernel() {
    int wid = (blockIdx.x * blockDim.x + threadIdx.x) >> 5;
    int lane = threadIdx.x & 31;
    if (wid >= NNODES) return;
    int half = lane >> 4, sub = lane & 15;
    int s = g_off[wid], e = g_off[wid + 1];
    float f[8];
#pragma unroll
    for (int j = 0; j < 8; j++) f[j] = 0.f;
    const __half* base = g_Ahi + 128;
    int i = s;
    for (; i + 8 <= e; i += 8) {
        int n0 = g_csrc[i     + half];
        int n1 = g_csrc[i + 2 + half];
        int n2 = g_csrc[i + 4 + half];
        int n3 = g_csrc[i + 6 + half];
        uint4 u0 = *(const uint4*)&base[(size_t)n0 * ASTRIDE + sub * 8];
        uint4 u1 = *(const uint4*)&base[(size_t)n1 * ASTRIDE + sub * 8];
        uint4 u2 = *(const uint4*)&base[(size_t)n2 * ASTRIDE + sub * 8];
        uint4 u3 = *(const uint4*)&base[(size_t)n3 * ASTRIDE + sub * 8];
        float2 p;
        p = __half22float2(*(__half2*)&u0.x); f[0] += p.x; f[1] += p.y;
        p = __half22float2(*(__half2*)&u0.y); f[2] += p.x; f[3] += p.y;
        p = __half22float2(*(__half2*)&u0.z); f[4] += p.x; f[5] += p.y;
        p = __half22float2(*(__half2*)&u0.w); f[6] += p.x; f[7] += p.y;
        p = __half22float2(*(__half2*)&u1.x); f[0] += p.x; f[1] += p.y;
        p = __half22float2(*(__half2*)&u1.y); f[2] += p.x; f[3] += p.y;
        p = __half22float2(*(__half2*)&u1.z); f[4] += p.x; f[5] += p.y;
        p = __half22float2(*(__half2*)&u1.w); f[6] += p.x; f[7] += p.y;
        p = __half22float2(*(__half2*)&u2.x); f[0] += p.x; f[1] += p.y;
        p = __half22float2(*(__half2*)&u2.y); f[2] += p.x; f[3] += p.y;
        p = __half22float2(*(__half2*)&u2.z); f[4] += p.x; f[5] += p.y;
        p = __half22float2(*(__half2*)&u2.w); f[6] += p.x; f[7] += p.y;
        p = __half22float2(*(__half2*)&u3.x); f[0] += p.x; f[1] += p.y;
        p = __half22float2(*(__half2*)&u3.y); f[2] += p.x; f[3] += p.y;
        p = __half22float2(*(__half2*)&u3.z); f[4] += p.x; f[5] += p.y;
        p = __half22float2(*(__half2*)&u3.w); f[6] += p.x; f[7] += p.y;
    }
    for (; i + 4 <= e; i += 4) {
        int n0 = g_csrc[i + half];
        int n1 = g_csrc[i + 2 + half];
        uint4 u0 = *(const uint4*)&base[(size_t)n0 * ASTRIDE + sub * 8];
        uint4 u1 = *(const uint4*)&base[(size_t)n1 * ASTRIDE + sub * 8];
        float2 p;
        p = __half22float2(*(__half2*)&u0.x); f[0] += p.x; f[1] += p.y;
        p = __half22float2(*(__half2*)&u0.y); f[2] += p.x; f[3] += p.y;
        p = __half22float2(*(__half2*)&u0.z); f[4] += p.x; f[5] += p.y;
        p = __half22float2(*(__half2*)&u0.w); f[6] += p.x; f[7] += p.y;
        p = __half22float2(*(__half2*)&u1.x); f[0] += p.x; f[1] += p.y;
        p = __half22float2(*(__half2*)&u1.y); f[2] += p.x; f[3] += p.y;
        p = __half22float2(*(__half2*)&u1.z); f[4] += p.x; f[5] += p.y;
        p = __half22float2(*(__half2*)&u1.w); f[6] += p.x; f[7] += p.y;
    }
    for (; i < e; i += 2) {
        if (i + half < e) {
            int n = g_csrc[i + half];
            uint4 u = *(const uint4*)&base[(size_t)n * ASTRIDE + sub * 8];
            float2 p;
            p = __half22float2(*(__half2*)&u.x); f[0] += p.x; f[1] += p.y;
            p = __half22float2(*(__half2*)&u.y); f[2] += p.x; f[3] += p.y;
            p = __half22float2(*(__half2*)&u.z); f[4] += p.x; f[5] += p.y;
            p = __half22float2(*(__half2*)&u.w); f[6] += p.x; f[7] += p.y;
        }
    }
#pragma unroll
    for (int j = 0; j < 8; j++)
        f[j] += __shfl_xor_sync(0xFFFFFFFF, f[j], 16);
    if (half == 0) {
        float inv = 1.0f / (float)max(e - s, 1);
        __half2 h01 = __float22half2_rn(make_float2(f[0] * inv, f[1] * inv));
        __half2 h23 = __float22half2_rn(make_float2(f[2] * inv, f[3] * inv));
        __half2 h45 = __float22half2_rn(make_float2(f[4] * inv, f[5] * inv));
        __half2 h67 = __float22half2_rn(make_float2(f[6] * inv, f[7] * inv));
        uint4 uh;
        uh.x = *(uint32_t*)&h01; uh.y = *(uint32_t*)&h23;
        uh.z = *(uint32_t*)&h45; uh.w = *(uint32_t*)&h67;
        *(uint4*)&g_Ahi[(size_t)wid * ASTRIDE + sub * 8] = uh;
    }
}

// ---------------- pipelined HMMA GEMM: A(fp16) @ Wh^T, cp.async double-buffer ----------------
#define SMSTR 72
#define CH    (128 * SMSTR)                       // halves per staged matrix
#define SM_BYTES (2 * 2 * CH * 2)                 // 2 buffers x {Ah, Wh} = 73728

__device__ __forceinline__ void ldsm4(uint32_t* r, uint32_t addr) {
    asm volatile("ldmatrix.sync.aligned.m8n8.x4.shared.b16 {%0,%1,%2,%3}, [%4];"
                 : "=r"(r[0]), "=r"(r[1]), "=r"(r[2]), "=r"(r[3]) : "r"(addr));
}
__device__ __forceinline__ void mma16816(float* c, const uint32_t* a, uint32_t b0, uint32_t b1) {
    asm volatile("mma.sync.aligned.m16n8k16.row.col.f32.f16.f16.f32 "
                 "{%0,%1,%2,%3}, {%4,%5,%6,%7}, {%8,%9}, {%0,%1,%2,%3};"
                 : "+f"(c[0]), "+f"(c[1]), "+f"(c[2]), "+f"(c[3])
                 : "r"(a[0]), "r"(a[1]), "r"(a[2]), "r"(a[3]), "r"(b0), "r"(b1));
}
__device__ __forceinline__ void cp16(uint32_t dst, const void* src, int szvalid) {
    asm volatile("cp.async.cg.shared.global [%0], [%1], 16, %2;"
                 :: "r"(dst), "l"(src), "r"(szvalid));
}
#define CP_COMMIT() asm volatile("cp.async.commit_group;" ::: "memory")
#define CP_WAIT1()  asm volatile("cp.async.wait_group 1;"  ::: "memory")

__global__ __launch_bounds__(256, 3) void sage_mma(
    const __half* __restrict__ Whg,
    const float* __restrict__ bias, float* __restrict__ hout,      // null for layers 1-2
    __half* __restrict__ selfhi,                                    // null for layer 3
    int Ktot)
{
    extern __shared__ __half sm[];
    int tid = threadIdx.x;
    int lane = tid & 31, wid = tid >> 5;
    int warpM = wid & 3, warpN = wid >> 2;
    int row0 = blockIdx.x * 128;
    uint32_t sb = (uint32_t)__cvta_generic_to_shared(sm);

    int str = tid >> 3, stc = (tid & 7) * 8;      // staging: row, col-start

    auto stage = [&](int b, int kc) {
#pragma unroll
        for (int it = 0; it < 4; it++) {
            int rr = str + it * 32;
            int grow = row0 + rr;
            int v = (grow < NNODES) ? 16 : 0;
            int gr = (grow < NNODES) ? grow : 0;
            uint32_t o = sb + (uint32_t)((b * 2 * CH + rr * SMSTR + stc) * 2);
            cp16(o,          &g_Ahi[(size_t)gr * ASTRIDE + kc * 64 + stc], v);
            cp16(o + CH * 2, &Whg[(size_t)rr * ASTRIDE + kc * 64 + stc], 16);
        }
        CP_COMMIT();
    };

    float acc[2][8][4];
#pragma unroll
    for (int a = 0; a < 2; a++)
#pragma unroll
        for (int b = 0; b < 8; b++)
#pragma unroll
            for (int c = 0; c < 4; c++) acc[a][b][c] = 0.f;

    int frow = (lane & 7) + ((lane >> 3) & 1) * 8;
    int fcol = (lane >> 4) * 8;

    int nch = Ktot >> 6;
    stage(0, 0);
    int buf = 0;
    for (int kc = 0; kc < nch; kc++) {
        if (kc + 1 < nch) stage(buf ^ 1, kc + 1);
        else              CP_COMMIT();
        CP_WAIT1();
        __syncthreads();

        uint32_t aB = sb + (uint32_t)((buf * 2 * CH) * 2);
        uint32_t hB = aB + CH * 2;

#pragma unroll
        for (int k16 = 0; k16 < 4; k16++) {
            int k0 = k16 * 16;
            uint32_t ah[2][4];
#pragma unroll
            for (int mf = 0; mf < 2; mf++) {
                uint32_t off = (uint32_t)(((warpM * 32 + mf * 16 + frow) * SMSTR + k0 + fcol) * 2);
                ldsm4(ah[mf], aB + off);
            }
#pragma unroll
            for (int nf2 = 0; nf2 < 4; nf2++) {
                uint32_t boff = (uint32_t)(((warpN * 64 + nf2 * 16 + frow) * SMSTR + k0 + fcol) * 2);
                uint32_t bh[4];
                ldsm4(bh, hB + boff);
#pragma unroll
                for (int mf = 0; mf < 2; mf++) {
#pragma unroll
                    for (int h = 0; h < 2; h++) {
                        float* c = acc[mf][nf2 * 2 + h];
                        mma16816(c, ah[mf], bh[h], bh[h + 2]);
                    }
                }
            }
        }
        __syncthreads();
        buf ^= 1;
    }

    // ---- epilogue ----
#pragma unroll
    for (int mf = 0; mf < 2; mf++) {
#pragma unroll
        for (int nf = 0; nf < 8; nf++) {
            int cc = warpN * 64 + nf * 8 + (lane & 3) * 2;
            float b0 = bias[cc], b1 = bias[cc + 1];
#pragma unroll
            for (int h = 0; h < 2; h++) {
                int rr = row0 + warpM * 32 + mf * 16 + (lane >> 2) + h * 8;
                if (rr < NNODES) {
                    float v0 = fmaxf(acc[mf][nf][h * 2 + 0] + b0, 0.f);
                    float v1 = fmaxf(acc[mf][nf][h * 2 + 1] + b1, 0.f);
                    if (hout)
                        *(float2*)&hout[(size_t)rr * 128 + cc] = make_float2(v0, v1);
                    if (selfhi) {
                        __half2 hi = __float22half2_rn(make_float2(v0, v1));
                        *(__half2*)&selfhi[(size_t)rr * ASTRIDE + 128 + cc] = hi;
                    }
                }
            }
        }
    }
}

// ---------------- fused pool + MLP ----------------
__device__ __forceinline__ int lower_bound_batch(const int* batch, int key) {
    int lo = 0, hi = NNODES;
    while (lo < hi) {
        int mid = (lo + hi) >> 1;
        if (batch[mid] < key) lo = mid + 1; else hi = mid;
    }
    return lo;
}
__global__ __launch_bounds__(DH) void poolmlp_kernel(
    const int* __restrict__ batch, const float* __restrict__ h,
    const float* __restrict__ W1, const float* __restrict__ bl1,
    const float* __restrict__ W2, const float* __restrict__ bl2,
    float* __restrict__ out)
{
    __shared__ int s_start, s_end;
    __shared__ float p[DH];
    __shared__ float hid[NEMB];
    int g = blockIdx.x;
    int t = threadIdx.x;
    if (t == 0) s_start = lower_bound_batch(batch, g);
    if (t == 1) s_end   = lower_bound_batch(batch, g + 1);
    __syncthreads();
    int start = s_start, end = s_end;
    float acc = 0.f;
#pragma unroll 4
    for (int n = start; n < end; n++)
        acc += h[(size_t)n * DH + t];
    p[t] = acc / (float)max(end - start, 1);
    __syncthreads();
    if (t < NEMB) {
        float s = bl1[t];
#pragma unroll 8
        for (int k = 0; k < DH; k++) s += p[k] * W1[k * NEMB + t];
        hid[t] = fmaxf(s, 0.f);
    }
    __syncthreads();
    if (t < NEMB) {
        float o = bl2[t];
#pragma unroll 8
        for (int j = 0; j < NEMB; j++) o += hid[j] * W2[j * NEMB + t];
        out[g * NEMB + t] = o;
    }
}

// ---------------- launch ----------------
extern "C" void kernel_launch(void* const* d_in, const int* in_sizes, int n_in,
                              void* d_out, int out_size) {
    const float* x     = (const float*)d_in[0];
    const int*   ei    = (const int*)d_in[1];      // int32 (JAX x64 disabled)
    const int*   src   = ei;
    const int*   dst   = ei + NEDGES;
    const int*   batch = (const int*)d_in[2];
    const float *Wl1 = (const float*)d_in[3],  *Wr1 = (const float*)d_in[4],  *b1 = (const float*)d_in[5];
    const float *Wl2 = (const float*)d_in[6],  *Wr2 = (const float*)d_in[7],  *b2 = (const float*)d_in[8];
    const float *Wl3 = (const float*)d_in[9],  *Wr3 = (const float*)d_in[10], *b3 = (const float*)d_in[11];
    const float *W1  = (const float*)d_in[12], *bl1 = (const float*)d_in[13];
    const float *W2  = (const float*)d_in[14], *bl2 = (const float*)d_in[15];

    float* h;    cudaGetSymbolAddress((void**)&h,  g_h);
    __half *Ahi, *W1h, *W2h, *W3h;
    cudaGetSymbolAddress((void**)&Ahi, g_Ahi);
    cudaGetSymbolAddress((void**)&W1h, g_W1h);
    cudaGetSymbolAddress((void**)&W2h, g_W2h);
    cudaGetSymbolAddress((void**)&W3h, g_W3h);

    cudaFuncSetAttribute(sage_mma, cudaFuncAttributeMaxDynamicSharedMemorySize, SM_BYTES);

    const int T = 256;
    int warp_blocks = (NNODES * 32 + T - 1) / T;

    // ---- fused prep (hist | x->fp16+self | W->fp16) (0), scan(1), fill(2) ----
    prep_fused<<<HIST_B + X2H_B + PREPW_B, T>>>(dst, x, Wl1, Wr1, Wl2, Wr2, Wl3, Wr3);
    scan_fused_kernel<<<NBLK, SCANB>>>();
    fill_kernel<<<(NEDGES + T - 1) / T, T>>>(src, dst);

    // ---- layer-1 aggregation at launch index 3 (profiled slot) ----
    agg64x_kernel<<<warp_blocks, T>>>();

    // ---- layer 1 GEMM (Ktot=128) ----
    sage_mma<<<NTILES, 256, SM_BYTES>>>(W1h, b1, (float*)nullptr, Ahi, 128);

    // ---- layer 2 ----
    agg128h_kernel<<<warp_blocks, T>>>();
    sage_mma<<<NTILES, 256, SM_BYTES>>>(W2h, b2, (float*)nullptr, Ahi, 256);

    // ---- layer 3 ----
    agg128h_kernel<<<warp_blocks, T>>>();
    sage_mma<<<NTILES, 256, SM_BYTES>>>(W3h, b3, h, (__half*)nullptr, 256);

    // ---- fused pool + MLP ----
    poolmlp_kernel<<<NG, DH>>>(batch, h, W1, bl1, W2, bl2, (float*)d_out);
}

// round 17
// speedup vs baseline: 1.1491x; 1.1491x over previous
#include <cuda_runtime.h>
#include <cuda_fp16.h>
#include <cstdint>

#define NNODES 100000
#define NEDGES 1600000
#define DIN    64
#define DH     128
#define NG     64
#define NEMB   64
#define SCANB  1024
#define NBLK   ((NNODES + SCANB - 1) / SCANB)   // 98
#define ASTRIDE 256                              // fp16 operand row stride (halves)
#define NTILES ((NNODES + 127) / 128)            // 782

// fused prep kernel block ranges
#define HIST_B  ((NEDGES + 255) / 256)                 // 6250
#define X2H_B   ((NNODES * (DIN / 2) + 255) / 256)     // 12500
#define PREPW_N (128 * 128 + 2 * 128 * 256)            // 81920
#define PREPW_B ((PREPW_N + 255) / 256)                // 320

// ---------------- scratch (static device memory; no allocation) ----------------
__device__ float  g_h[(size_t)NNODES * DH];
__device__ __align__(16) __half g_Ahi[(size_t)NNODES * ASTRIDE];
__device__ __align__(16) __half g_xh [(size_t)NNODES * DIN];     // fp16 copy of x
__device__ __align__(16) __half g_W1h[128 * ASTRIDE];
__device__ __align__(16) __half g_W2h[128 * ASTRIDE];
__device__ __align__(16) __half g_W3h[128 * ASTRIDE];
__device__ int    g_deg_i[NNODES];      // zeroed inside scan kernel for next call
__device__ int    g_off[NNODES + 1];
__device__ int    g_cursor[NNODES];
__device__ int    g_aggr[NBLK];
__device__ int    g_scan_cnt;
__device__ int    g_csrc[NEDGES];

// ---------------- fused prep: dst-histogram | x->fp16 (+ self half) | W->fp16 ----------------
__global__ void prep_fused(const int* __restrict__ dst, const float* __restrict__ x,
                           const float* __restrict__ Wl1, const float* __restrict__ Wr1,
                           const float* __restrict__ Wl2, const float* __restrict__ Wr2,
                           const float* __restrict__ Wl3, const float* __restrict__ Wr3) {
    int b = blockIdx.x;
    if (b < HIST_B) {
        int e = b * 256 + threadIdx.x;
        if (e < NEDGES) atomicAdd(&g_deg_i[dst[e]], 1);
        return;
    }
    b -= HIST_B;
    if (b < X2H_B) {
        int i = b * 256 + threadIdx.x;               // half2 index
        if (i < NNODES * (DIN / 2)) {
            int n = i >> 5, cp = i & 31;
            float2 v = ((const float2*)x)[(size_t)n * 32 + cp];
            __half2 hv = __float22half2_rn(v);
            *(__half2*)&g_xh [(size_t)n * DIN + cp * 2]           = hv;
            *(__half2*)&g_Ahi[(size_t)n * ASTRIDE + 64 + cp * 2]  = hv;  // self half
        }
        return;
    }
    b -= X2H_B;
    {
        int idx = b * 256 + threadIdx.x;
        const float *Wl, *Wr;
        __half *wh;
        int K, local;
        if (idx < 128 * 128) {
            Wl = Wl1; Wr = Wr1; K = 64;  local = idx; wh = g_W1h;
        } else if (idx < 128 * 128 + 128 * 256) {
            Wl = Wl2; Wr = Wr2; K = 128; local = idx - 128 * 128; wh = g_W2h;
        } else if (idx < PREPW_N) {
            Wl = Wl3; Wr = Wr3; K = 128; local = idx - 128 * 128 - 128 * 256; wh = g_W3h;
        } else return;
        int Ktot = 2 * K;
        int n = local / Ktot, k = local % Ktot;
        float w = (k < K) ? Wl[k * 128 + n] : Wr[(k - K) * 128 + n];
        wh[(size_t)n * ASTRIDE + k] = __float2half_rn(w);
    }
}

// ---------------- fused exclusive scan (decoupled aggregates, 98 co-resident blocks) ----------------
__global__ __launch_bounds__(SCANB) void scan_fused_kernel() {
    __shared__ int sh[SCANB];
    __shared__ int s_base;
    int b = blockIdx.x;
    int i = b * SCANB + threadIdx.x;
    int v = (i < NNODES) ? g_deg_i[i] : 0;
    int x = v;
    sh[threadIdx.x] = x;
    __syncthreads();
#pragma unroll
    for (int d = 1; d < SCANB; d <<= 1) {
        int t = (threadIdx.x >= d) ? sh[threadIdx.x - d] : 0;
        __syncthreads();
        x += t;
        sh[threadIdx.x] = x;
        __syncthreads();
    }
    if (threadIdx.x == SCANB - 1) {
        g_aggr[b] = x;
        __threadfence();
        atomicAdd(&g_scan_cnt, 1);
    }
    if (threadIdx.x == 0) {
        while (atomicAdd(&g_scan_cnt, 0) < NBLK) { }
    }
    __syncthreads();
    __shared__ int red[128];
    if (threadIdx.x < 128) {
        int t = threadIdx.x;
        red[t] = (t < b) ? g_aggr[t] : 0;
    }
    __syncthreads();
    if (threadIdx.x < 64)  red[threadIdx.x] += red[threadIdx.x + 64];
    __syncthreads();
    if (threadIdx.x < 32) {
        int s = red[threadIdx.x] + red[threadIdx.x + 32];
#pragma unroll
        for (int o = 16; o > 0; o >>= 1)
            s += __shfl_down_sync(0xFFFFFFFF, s, o);
        if (threadIdx.x == 0) s_base = s;
    }
    __syncthreads();
    int base = s_base;
    if (i < NNODES) {
        int o = base + x - v;
        g_off[i] = o;
        g_cursor[i] = o;
        g_deg_i[i] = 0;
    }
    if (i == 0) g_off[NNODES] = NEDGES;
}

__global__ void fill_kernel(const int* __restrict__ src, const int* __restrict__ dst) {
    int e = blockIdx.x * blockDim.x + threadIdx.x;
    if (e == 0) g_scan_cnt = 0;
    if (e < NEDGES) {
        int t = dst[e];
        int slot = atomicAdd(&g_cursor[t], 1);
        g_csrc[slot] = src[e];
    }
}

// ---------------- layer-1 aggregation: fp16 gather, 8-edge unroll (MLP 4/lane) ----------------
__global__ __launch_bounds__(256) void agg64x_kernel() {
    int wid = (blockIdx.x * blockDim.x + threadIdx.x) >> 5;
    int lane = threadIdx.x & 31;
    if (wid >= NNODES) return;
    int half = lane >> 4, sub = lane & 15;
    int s = g_off[wid], e = g_off[wid + 1];
    float ax = 0.f, ay = 0.f, az = 0.f, aw = 0.f;
    const uint2* xh = (const uint2*)g_xh;     // 16 uint2 per 64-col row
    int i = s;
    for (; i + 8 <= e; i += 8) {
        int n0 = g_csrc[i     + half];
        int n1 = g_csrc[i + 2 + half];
        int n2 = g_csrc[i + 4 + half];
        int n3 = g_csrc[i + 6 + half];
        uint2 u0 = xh[(size_t)n0 * 16 + sub];
        uint2 u1 = xh[(size_t)n1 * 16 + sub];
        uint2 u2 = xh[(size_t)n2 * 16 + sub];
        uint2 u3 = xh[(size_t)n3 * 16 + sub];
        float2 p;
        p = __half22float2(*(__half2*)&u0.x); ax += p.x; ay += p.y;
        p = __half22float2(*(__half2*)&u0.y); az += p.x; aw += p.y;
        p = __half22float2(*(__half2*)&u1.x); ax += p.x; ay += p.y;
        p = __half22float2(*(__half2*)&u1.y); az += p.x; aw += p.y;
        p = __half22float2(*(__half2*)&u2.x); ax += p.x; ay += p.y;
        p = __half22float2(*(__half2*)&u2.y); az += p.x; aw += p.y;
        p = __half22float2(*(__half2*)&u3.x); ax += p.x; ay += p.y;
        p = __half22float2(*(__half2*)&u3.y); az += p.x; aw += p.y;
    }
    for (; i + 4 <= e; i += 4) {
        int n0 = g_csrc[i + half];
        int n1 = g_csrc[i + 2 + half];
        uint2 u0 = xh[(size_t)n0 * 16 + sub];
        uint2 u1 = xh[(size_t)n1 * 16 + sub];
        float2 p;
        p = __half22float2(*(__half2*)&u0.x); ax += p.x; ay += p.y;
        p = __half22float2(*(__half2*)&u0.y); az += p.x; aw += p.y;
        p = __half22float2(*(__half2*)&u1.x); ax += p.x; ay += p.y;
        p = __half22float2(*(__half2*)&u1.y); az += p.x; aw += p.y;
    }
    for (; i < e; i += 2) {
        if (i + half < e) {
            int n = g_csrc[i + half];
            uint2 u = xh[(size_t)n * 16 + sub];
            float2 p;
            p = __half22float2(*(__half2*)&u.x); ax += p.x; ay += p.y;
            p = __half22float2(*(__half2*)&u.y); az += p.x; aw += p.y;
        }
    }
    ax += __shfl_xor_sync(0xFFFFFFFF, ax, 16);
    ay += __shfl_xor_sync(0xFFFFFFFF, ay, 16);
    az += __shfl_xor_sync(0xFFFFFFFF, az, 16);
    aw += __shfl_xor_sync(0xFFFFFFFF, aw, 16);
    if (half == 0) {
        float inv = 1.0f / (float)max(e - s, 1);
        __half2 h0 = __float22half2_rn(make_float2(ax * inv, ay * inv));
        __half2 h1 = __float22half2_rn(make_float2(az * inv, aw * inv));
        uint2 uh;
        uh.x = *(uint32_t*)&h0; uh.y = *(uint32_t*)&h1;
        *(uint2*)&g_Ahi[(size_t)wid * ASTRIDE + sub * 4] = uh;
    }
}

// ---------------- layer-2/3 aggregation: fp16 shadow, 8-edge unroll (MLP 4/lane) ----------------
__global__ __launch_bounds__(256) void agg128h_kernel() {
    int wid = (blockIdx.x * blockDim.x + threadIdx.x) >> 5;
    int lane = threadIdx.x & 31;
    if (wid >= NNODES) return;
    int half = lane >> 4, sub = lane & 15;
    int s = g_off[wid], e = g_off[wid + 1];
    float f[8];
#pragma unroll
    for (int j = 0; j < 8; j++) f[j] = 0.f;
    const __half* base = g_Ahi + 128;
    int i = s;
    for (; i + 8 <= e; i += 8) {
        int n0 = g_csrc[i     + half];
        int n1 = g_csrc[i + 2 + half];
        int n2 = g_csrc[i + 4 + half];
        int n3 = g_csrc[i + 6 + half];
        uint4 u0 = *(const uint4*)&base[(size_t)n0 * ASTRIDE + sub * 8];
        uint4 u1 = *(const uint4*)&base[(size_t)n1 * ASTRIDE + sub * 8];
        uint4 u2 = *(const uint4*)&base[(size_t)n2 * ASTRIDE + sub * 8];
        uint4 u3 = *(const uint4*)&base[(size_t)n3 * ASTRIDE + sub * 8];
        float2 p;
        p = __half22float2(*(__half2*)&u0.x); f[0] += p.x; f[1] += p.y;
        p = __half22float2(*(__half2*)&u0.y); f[2] += p.x; f[3] += p.y;
        p = __half22float2(*(__half2*)&u0.z); f[4] += p.x; f[5] += p.y;
        p = __half22float2(*(__half2*)&u0.w); f[6] += p.x; f[7] += p.y;
        p = __half22float2(*(__half2*)&u1.x); f[0] += p.x; f[1] += p.y;
        p = __half22float2(*(__half2*)&u1.y); f[2] += p.x; f[3] += p.y;
        p = __half22float2(*(__half2*)&u1.z); f[4] += p.x; f[5] += p.y;
        p = __half22float2(*(__half2*)&u1.w); f[6] += p.x; f[7] += p.y;
        p = __half22float2(*(__half2*)&u2.x); f[0] += p.x; f[1] += p.y;
        p = __half22float2(*(__half2*)&u2.y); f[2] += p.x; f[3] += p.y;
        p = __half22float2(*(__half2*)&u2.z); f[4] += p.x; f[5] += p.y;
        p = __half22float2(*(__half2*)&u2.w); f[6] += p.x; f[7] += p.y;
        p = __half22float2(*(__half2*)&u3.x); f[0] += p.x; f[1] += p.y;
        p = __half22float2(*(__half2*)&u3.y); f[2] += p.x; f[3] += p.y;
        p = __half22float2(*(__half2*)&u3.z); f[4] += p.x; f[5] += p.y;
        p = __half22float2(*(__half2*)&u3.w); f[6] += p.x; f[7] += p.y;
    }
    for (; i + 4 <= e; i += 4) {
        int n0 = g_csrc[i + half];
        int n1 = g_csrc[i + 2 + half];
        uint4 u0 = *(const uint4*)&base[(size_t)n0 * ASTRIDE + sub * 8];
        uint4 u1 = *(const uint4*)&base[(size_t)n1 * ASTRIDE + sub * 8];
        float2 p;
        p = __half22float2(*(__half2*)&u0.x); f[0] += p.x; f[1] += p.y;
        p = __half22float2(*(__half2*)&u0.y); f[2] += p.x; f[3] += p.y;
        p = __half22float2(*(__half2*)&u0.z); f[4] += p.x; f[5] += p.y;
        p = __half22float2(*(__half2*)&u0.w); f[6] += p.x; f[7] += p.y;
        p = __half22float2(*(__half2*)&u1.x); f[0] += p.x; f[1] += p.y;
        p = __half22float2(*(__half2*)&u1.y); f[2] += p.x; f[3] += p.y;
        p = __half22float2(*(__half2*)&u1.z); f[4] += p.x; f[5] += p.y;
        p = __half22float2(*(__half2*)&u1.w); f[6] += p.x; f[7] += p.y;
    }
    for (; i < e; i += 2) {
        if (i + half < e) {
            int n = g_csrc[i + half];
            uint4 u = *(const uint4*)&base[(size_t)n * ASTRIDE + sub * 8];
            float2 p;
            p = __half22float2(*(__half2*)&u.x); f[0] += p.x; f[1] += p.y;
            p = __half22float2(*(__half2*)&u.y); f[2] += p.x; f[3] += p.y;
            p = __half22float2(*(__half2*)&u.z); f[4] += p.x; f[5] += p.y;
            p = __half22float2(*(__half2*)&u.w); f[6] += p.x; f[7] += p.y;
        }
    }
#pragma unroll
    for (int j = 0; j < 8; j++)
        f[j] += __shfl_xor_sync(0xFFFFFFFF, f[j], 16);
    if (half == 0) {
        float inv = 1.0f / (float)max(e - s, 1);
        __half2 h01 = __float22half2_rn(make_float2(f[0] * inv, f[1] * inv));
        __half2 h23 = __float22half2_rn(make_float2(f[2] * inv, f[3] * inv));
        __half2 h45 = __float22half2_rn(make_float2(f[4] * inv, f[5] * inv));
        __half2 h67 = __float22half2_rn(make_float2(f[6] * inv, f[7] * inv));
        uint4 uh;
        uh.x = *(uint32_t*)&h01; uh.y = *(uint32_t*)&h23;
        uh.z = *(uint32_t*)&h45; uh.w = *(uint32_t*)&h67;
        *(uint4*)&g_Ahi[(size_t)wid * ASTRIDE + sub * 8] = uh;
    }
}

// ---------------- pipelined HMMA GEMM: A(fp16) @ Wh^T, cp.async double-buffer ----------------
#define SMSTR 72
#define CH    (128 * SMSTR)                       // halves per staged matrix
#define SM_BYTES (2 * 2 * CH * 2)                 // 2 buffers x {Ah, Wh} = 73728

__device__ __forceinline__ void ldsm4(uint32_t* r, uint32_t addr) {
    asm volatile("ldmatrix.sync.aligned.m8n8.x4.shared.b16 {%0,%1,%2,%3}, [%4];"
                 : "=r"(r[0]), "=r"(r[1]), "=r"(r[2]), "=r"(r[3]) : "r"(addr));
}
__device__ __forceinline__ void mma16816(float* c, const uint32_t* a, uint32_t b0, uint32_t b1) {
    asm volatile("mma.sync.aligned.m16n8k16.row.col.f32.f16.f16.f32 "
                 "{%0,%1,%2,%3}, {%4,%5,%6,%7}, {%8,%9}, {%0,%1,%2,%3};"
                 : "+f"(c[0]), "+f"(c[1]), "+f"(c[2]), "+f"(c[3])
                 : "r"(a[0]), "r"(a[1]), "r"(a[2]), "r"(a[3]), "r"(b0), "r"(b1));
}
__device__ __forceinline__ void cp16(uint32_t dst, const void* src, int szvalid) {
    asm volatile("cp.async.cg.shared.global [%0], [%1], 16, %2;"
                 :: "r"(dst), "l"(src), "r"(szvalid));
}
#define CP_COMMIT() asm volatile("cp.async.commit_group;" ::: "memory")
#define CP_WAIT1()  asm volatile("cp.async.wait_group 1;"  ::: "memory")

__global__ __launch_bounds__(256, 2) void sage_mma(
    const __half* __restrict__ Whg,
    const float* __restrict__ bias, float* __restrict__ hout,      // null for layers 1-2
    __half* __restrict__ selfhi,                                    // null for layer 3
    int Ktot)
{
    extern __shared__ __half sm[];
    int tid = threadIdx.x;
    int lane = tid & 31, wid = tid >> 5;
    int warpM = wid & 3, warpN = wid >> 2;
    int row0 = blockIdx.x * 128;
    uint32_t sb = (uint32_t)__cvta_generic_to_shared(sm);

    int str = tid >> 3, stc = (tid & 7) * 8;      // staging: row, col-start

    auto stage = [&](int b, int kc) {
#pragma unroll
        for (int it = 0; it < 4; it++) {
            int rr = str + it * 32;
            int grow = row0 + rr;
            int v = (grow < NNODES) ? 16 : 0;
            int gr = (grow < NNODES) ? grow : 0;
            uint32_t o = sb + (uint32_t)((b * 2 * CH + rr * SMSTR + stc) * 2);
            cp16(o,          &g_Ahi[(size_t)gr * ASTRIDE + kc * 64 + stc], v);
            cp16(o + CH * 2, &Whg[(size_t)rr * ASTRIDE + kc * 64 + stc], 16);
        }
        CP_COMMIT();
    };

    float acc[2][8][4];
#pragma unroll
    for (int a = 0; a < 2; a++)
#pragma unroll
        for (int b = 0; b < 8; b++)
#pragma unroll
            for (int c = 0; c < 4; c++) acc[a][b][c] = 0.f;

    int frow = (lane & 7) + ((lane >> 3) & 1) * 8;
    int fcol = (lane >> 4) * 8;

    int nch = Ktot >> 6;
    stage(0, 0);
    int buf = 0;
    for (int kc = 0; kc < nch; kc++) {
        if (kc + 1 < nch) stage(buf ^ 1, kc + 1);
        else              CP_COMMIT();
        CP_WAIT1();
        __syncthreads();

        uint32_t aB = sb + (uint32_t)((buf * 2 * CH) * 2);
        uint32_t hB = aB + CH * 2;

#pragma unroll
        for (int k16 = 0; k16 < 4; k16++) {
            int k0 = k16 * 16;
            uint32_t ah[2][4];
#pragma unroll
            for (int mf = 0; mf < 2; mf++) {
                uint32_t off = (uint32_t)(((warpM * 32 + mf * 16 + frow) * SMSTR + k0 + fcol) * 2);
                ldsm4(ah[mf], aB + off);
            }
#pragma unroll
            for (int nf2 = 0; nf2 < 4; nf2++) {
                uint32_t boff = (uint32_t)(((warpN * 64 + nf2 * 16 + frow) * SMSTR + k0 + fcol) * 2);
                uint32_t bh[4];
                ldsm4(bh, hB + boff);
#pragma unroll
                for (int mf = 0; mf < 2; mf++) {
#pragma unroll
                    for (int h = 0; h < 2; h++) {
                        float* c = acc[mf][nf2 * 2 + h];
                        mma16816(c, ah[mf], bh[h], bh[h + 2]);
                    }
                }
            }
        }
        __syncthreads();
        buf ^= 1;
    }

    // ---- epilogue ----
#pragma unroll
    for (int mf = 0; mf < 2; mf++) {
#pragma unroll
        for (int nf = 0; nf < 8; nf++) {
            int cc = warpN * 64 + nf * 8 + (lane & 3) * 2;
            float b0 = bias[cc], b1 = bias[cc + 1];
#pragma unroll
            for (int h = 0; h < 2; h++) {
                int rr = row0 + warpM * 32 + mf * 16 + (lane >> 2) + h * 8;
                if (rr < NNODES) {
                    float v0 = fmaxf(acc[mf][nf][h * 2 + 0] + b0, 0.f);
                    float v1 = fmaxf(acc[mf][nf][h * 2 + 1] + b1, 0.f);
                    if (hout)
                        *(float2*)&hout[(size_t)rr * 128 + cc] = make_float2(v0, v1);
                    if (selfhi) {
                        __half2 hi = __float22half2_rn(make_float2(v0, v1));
                        *(__half2*)&selfhi[(size_t)rr * ASTRIDE + 128 + cc] = hi;
                    }
                }
            }
        }
    }
}

// ---------------- fused pool + MLP ----------------
__device__ __forceinline__ int lower_bound_batch(const int* batch, int key) {
    int lo = 0, hi = NNODES;
    while (lo < hi) {
        int mid = (lo + hi) >> 1;
        if (batch[mid] < key) lo = mid + 1; else hi = mid;
    }
    return lo;
}
__global__ __launch_bounds__(DH) void poolmlp_kernel(
    const int* __restrict__ batch, const float* __restrict__ h,
    const float* __restrict__ W1, const float* __restrict__ bl1,
    const float* __restrict__ W2, const float* __restrict__ bl2,
    float* __restrict__ out)
{
    __shared__ int s_start, s_end;
    __shared__ float p[DH];
    __shared__ float hid[NEMB];
    int g = blockIdx.x;
    int t = threadIdx.x;
    if (t == 0) s_start = lower_bound_batch(batch, g);
    if (t == 1) s_end   = lower_bound_batch(batch, g + 1);
    __syncthreads();
    int start = s_start, end = s_end;
    float acc = 0.f;
#pragma unroll 4
    for (int n = start; n < end; n++)
        acc += h[(size_t)n * DH + t];
    p[t] = acc / (float)max(end - start, 1);
    __syncthreads();
    if (t < NEMB) {
        float s = bl1[t];
#pragma unroll 8
        for (int k = 0; k < DH; k++) s += p[k] * W1[k * NEMB + t];
        hid[t] = fmaxf(s, 0.f);
    }
    __syncthreads();
    if (t < NEMB) {
        float o = bl2[t];
#pragma unroll 8
        for (int j = 0; j < NEMB; j++) o += hid[j] * W2[j * NEMB + t];
        out[g * NEMB + t] = o;
    }
}

// ---------------- launch ----------------
extern "C" void kernel_launch(void* const* d_in, const int* in_sizes, int n_in,
                              void* d_out, int out_size) {
    const float* x     = (const float*)d_in[0];
    const int*   ei    = (const int*)d_in[1];      // int32 (JAX x64 disabled)
    const int*   src   = ei;
    const int*   dst   = ei + NEDGES;
    const int*   batch = (const int*)d_in[2];
    const float *Wl1 = (const float*)d_in[3],  *Wr1 = (const float*)d_in[4],  *b1 = (const float*)d_in[5];
    const float *Wl2 = (const float*)d_in[6],  *Wr2 = (const float*)d_in[7],  *b2 = (const float*)d_in[8];
    const float *Wl3 = (const float*)d_in[9],  *Wr3 = (const float*)d_in[10], *b3 = (const float*)d_in[11];
    const float *W1  = (const float*)d_in[12], *bl1 = (const float*)d_in[13];
    const float *W2  = (const float*)d_in[14], *bl2 = (const float*)d_in[15];

    float* h;    cudaGetSymbolAddress((void**)&h,  g_h);
    __half *Ahi, *W1h, *W2h, *W3h;
    cudaGetSymbolAddress((void**)&Ahi, g_Ahi);
    cudaGetSymbolAddress((void**)&W1h, g_W1h);
    cudaGetSymbolAddress((void**)&W2h, g_W2h);
    cudaGetSymbolAddress((void**)&W3h, g_W3h);

    cudaFuncSetAttribute(sage_mma, cudaFuncAttributeMaxDynamicSharedMemorySize, SM_BYTES);

    const int T = 256;
    int warp_blocks = (NNODES * 32 + T - 1) / T;

    // ---- fused prep (hist | x->fp16+self | W->fp16) (0), scan(1), fill(2) ----
    prep_fused<<<HIST_B + X2H_B + PREPW_B, T>>>(dst, x, Wl1, Wr1, Wl2, Wr2, Wl3, Wr3);
    scan_fused_kernel<<<NBLK, SCANB>>>();
    fill_kernel<<<(NEDGES + T - 1) / T, T>>>(src, dst);

    // ---- layer-1 aggregation at launch index 3 (profiled slot) ----
    agg64x_kernel<<<warp_blocks, T>>>();

    // ---- layer 1 GEMM (Ktot=128) ----
    sage_mma<<<NTILES, 256, SM_BYTES>>>(W1h, b1, (float*)nullptr, Ahi, 128);

    // ---- layer 2 ----
    agg128h_kernel<<<warp_blocks, T>>>();
    sage_mma<<<NTILES, 256, SM_BYTES>>>(W2h, b2, (float*)nullptr, Ahi, 256);

    // ---- layer 3 ----
    agg128h_kernel<<<warp_blocks, T>>>();
    sage_mma<<<NTILES, 256, SM_BYTES>>>(W3h, b3, h, (__half*)nullptr, 256);

    // ---- fused pool + MLP ----
    poolmlp_kernel<<<NG, DH>>>(batch, h, W1, bl1, W2, bl2, (float*)d_out);
}